// round 3
// baseline (speedup 1.0000x reference)
#include <cuda_runtime.h>

#define NN 100000
#define NE 3200000
#define DIN 128
#define HD 16
#define SCAN_B 512
#define NSB ((NN + SCAN_B - 1) / SCAN_B)   // 196

// ---- scratch (static __device__, no allocation) ----
__device__ int    g_deg[NN];
__device__ float  g_dis[NN];
__device__ int    g_rowptr[NN + 1];
__device__ int    g_cursor[NN];
__device__ int    g_col[NE];
__device__ int    g_bsum[NSB];
__device__ int    g_boff[NSB];
__device__ float4 g_feat1[NN * 4];   // (x@W1) * dis[row], 16 floats/node
__device__ float4 g_h1[NN * 4];      // relu(layer1), later reused as h2
__device__ float4 g_feat2[NN * 4];   // (h1@W2) * dis[row]

__device__ __forceinline__ void fma4(float s, const float4 w, float4& a) {
    a.x = fmaf(s, w.x, a.x);
    a.y = fmaf(s, w.y, a.y);
    a.z = fmaf(s, w.z, a.z);
    a.w = fmaf(s, w.w, a.w);
}

// ---- degree / CSR build ----
__global__ void k_zero() {
    int i = blockIdx.x * blockDim.x + threadIdx.x;
    if (i < NN) g_deg[i] = 0;
}

__global__ void k_count(const int* __restrict__ dst) {
    int e = blockIdx.x * blockDim.x + threadIdx.x;
    if (e < NE) atomicAdd(&g_deg[dst[e]], 1);
}

__global__ void k_dis() {
    int i = blockIdx.x * blockDim.x + threadIdx.x;
    if (i < NN) g_dis[i] = rsqrtf((float)(g_deg[i] + 1));  // +1 self-loop
}

__global__ void k_scan_partial() {
    __shared__ int sh[SCAN_B];
    int i = blockIdx.x * SCAN_B + threadIdx.x;
    sh[threadIdx.x] = (i < NN) ? g_deg[i] : 0;
    __syncthreads();
    for (int off = SCAN_B / 2; off > 0; off >>= 1) {
        if (threadIdx.x < off) sh[threadIdx.x] += sh[threadIdx.x + off];
        __syncthreads();
    }
    if (threadIdx.x == 0) g_bsum[blockIdx.x] = sh[0];
}

__global__ void k_scan_bsum() {
    int run = 0;
    for (int b = 0; b < NSB; b++) { g_boff[b] = run; run += g_bsum[b]; }
}

__global__ void k_scan_final() {
    __shared__ int sh[SCAN_B];
    int i = blockIdx.x * SCAN_B + threadIdx.x;
    int v = (i < NN) ? g_deg[i] : 0;
    sh[threadIdx.x] = v;
    __syncthreads();
    for (int off = 1; off < SCAN_B; off <<= 1) {
        int t = (threadIdx.x >= off) ? sh[threadIdx.x - off] : 0;
        __syncthreads();
        sh[threadIdx.x] += t;
        __syncthreads();
    }
    int excl = g_boff[blockIdx.x] + sh[threadIdx.x] - v;  // exclusive prefix
    if (i < NN) { g_rowptr[i] = excl; g_cursor[i] = excl; }
    if (i == 0) g_rowptr[NN] = NE;
}

__global__ void k_fill(const int* __restrict__ src,
                       const int* __restrict__ dst) {
    int e = blockIdx.x * blockDim.x + threadIdx.x;
    if (e < NE) {
        int d = dst[e];
        int p = atomicAdd(&g_cursor[d], 1);
        g_col[p] = src[e];
    }
}

// ---- gemm1: feat1[row] = (x[row] @ W1) * dis[row] ----
__global__ void k_gemm1(const float* __restrict__ x,
                        const float* __restrict__ W1) {
    __shared__ float4 w4[DIN * HD / 4];  // 512 float4 = 8KB
    for (int t = threadIdx.x; t < DIN * HD / 4; t += blockDim.x)
        w4[t] = ((const float4*)W1)[t];
    __syncthreads();

    int row = blockIdx.x * blockDim.x + threadIdx.x;
    if (row >= NN) return;

    float4 a0 = {0.f, 0.f, 0.f, 0.f}, a1 = a0, a2 = a0, a3 = a0;
    const float4* xr = (const float4*)(x + (size_t)row * DIN);
    #pragma unroll 8
    for (int kk = 0; kk < DIN / 4; kk++) {
        float4 xv = xr[kk];
        const float4* wr = &w4[(size_t)(kk * 4) * 4];
        fma4(xv.x, wr[0],  a0); fma4(xv.x, wr[1],  a1); fma4(xv.x, wr[2],  a2); fma4(xv.x, wr[3],  a3);
        fma4(xv.y, wr[4],  a0); fma4(xv.y, wr[5],  a1); fma4(xv.y, wr[6],  a2); fma4(xv.y, wr[7],  a3);
        fma4(xv.z, wr[8],  a0); fma4(xv.z, wr[9],  a1); fma4(xv.z, wr[10], a2); fma4(xv.z, wr[11], a3);
        fma4(xv.w, wr[12], a0); fma4(xv.w, wr[13], a1); fma4(xv.w, wr[14], a2); fma4(xv.w, wr[15], a3);
    }
    float s = g_dis[row];
    a0.x *= s; a0.y *= s; a0.z *= s; a0.w *= s;
    a1.x *= s; a1.y *= s; a1.z *= s; a1.w *= s;
    a2.x *= s; a2.y *= s; a2.z *= s; a2.w *= s;
    a3.x *= s; a3.y *= s; a3.z *= s; a3.w *= s;
    g_feat1[row * 4 + 0] = a0;
    g_feat1[row * 4 + 1] = a1;
    g_feat1[row * 4 + 2] = a2;
    g_feat1[row * 4 + 3] = a3;
}

// ---- aggregation layer 1: h1 = relu(dis * (self + sum_in feat1[src]) + b1) ----
__global__ void k_agg1(const float* __restrict__ b1) {
    int t = blockIdx.x * blockDim.x + threadIdx.x;
    int node = t >> 2, q = t & 3;
    if (node >= NN) return;

    float4 acc = g_feat1[node * 4 + q];  // self loop term
    int s = g_rowptr[node], e = g_rowptr[node + 1];
    for (int j = s; j < e; j++) {
        int c = g_col[j];
        float4 v = g_feat1[c * 4 + q];
        acc.x += v.x; acc.y += v.y; acc.z += v.z; acc.w += v.w;
    }
    float ds = g_dis[node];
    float4 bb = ((const float4*)b1)[q];
    float4 h;
    h.x = fmaxf(fmaf(acc.x, ds, bb.x), 0.f);
    h.y = fmaxf(fmaf(acc.y, ds, bb.y), 0.f);
    h.z = fmaxf(fmaf(acc.z, ds, bb.z), 0.f);
    h.w = fmaxf(fmaf(acc.w, ds, bb.w), 0.f);
    g_h1[node * 4 + q] = h;
}

// ---- gemm2: feat2[row] = (h1[row] @ W2) * dis[row] ----
__global__ void k_gemm2(const float* __restrict__ W2) {
    __shared__ float4 w4[HD * HD / 4];  // 64 float4
    for (int t = threadIdx.x; t < HD * HD / 4; t += blockDim.x)
        w4[t] = ((const float4*)W2)[t];
    __syncthreads();

    int row = blockIdx.x * blockDim.x + threadIdx.x;
    if (row >= NN) return;

    float4 h0 = g_h1[row * 4 + 0];
    float4 h1 = g_h1[row * 4 + 1];
    float4 h2 = g_h1[row * 4 + 2];
    float4 h3 = g_h1[row * 4 + 3];
    float hv[HD] = {h0.x, h0.y, h0.z, h0.w, h1.x, h1.y, h1.z, h1.w,
                    h2.x, h2.y, h2.z, h2.w, h3.x, h3.y, h3.z, h3.w};

    float4 a0 = {0.f, 0.f, 0.f, 0.f}, a1 = a0, a2 = a0, a3 = a0;
    #pragma unroll
    for (int k = 0; k < HD; k++) {
        float s = hv[k];
        const float4* wr = &w4[k * 4];
        fma4(s, wr[0], a0); fma4(s, wr[1], a1); fma4(s, wr[2], a2); fma4(s, wr[3], a3);
    }
    float s = g_dis[row];
    a0.x *= s; a0.y *= s; a0.z *= s; a0.w *= s;
    a1.x *= s; a1.y *= s; a1.z *= s; a1.w *= s;
    a2.x *= s; a2.y *= s; a2.z *= s; a2.w *= s;
    a3.x *= s; a3.y *= s; a3.z *= s; a3.w *= s;
    g_feat2[row * 4 + 0] = a0;
    g_feat2[row * 4 + 1] = a1;
    g_feat2[row * 4 + 2] = a2;
    g_feat2[row * 4 + 3] = a3;
}

// ---- aggregation layer 2: h2 = relu(dis*(self + sum) + b2), stored into g_h1 ----
__global__ void k_agg2(const float* __restrict__ b2) {
    int t = blockIdx.x * blockDim.x + threadIdx.x;
    int node = t >> 2, q = t & 3;
    if (node >= NN) return;

    float4 acc = g_feat2[node * 4 + q];  // self loop
    int s = g_rowptr[node], e = g_rowptr[node + 1];
    for (int j = s; j < e; j++) {
        int c = g_col[j];
        float4 v = g_feat2[c * 4 + q];
        acc.x += v.x; acc.y += v.y; acc.z += v.z; acc.w += v.w;
    }
    float ds = g_dis[node];
    float4 bb = ((const float4*)b2)[q];
    float4 h;
    h.x = fmaxf(fmaf(acc.x, ds, bb.x), 0.f);
    h.y = fmaxf(fmaf(acc.y, ds, bb.y), 0.f);
    h.z = fmaxf(fmaf(acc.z, ds, bb.z), 0.f);
    h.w = fmaxf(fmaf(acc.w, ds, bb.w), 0.f);
    g_h1[node * 4 + q] = h;   // reuse g_h1 as h2 storage
}

// ---- final linear head: out[i] = h2[i] . Wl + bl ----
__global__ void k_head(const float* __restrict__ Wl,
                       const float* __restrict__ bl,
                       float* __restrict__ out) {
    int i = blockIdx.x * blockDim.x + threadIdx.x;
    if (i >= NN) return;
    float4 h0 = g_h1[i * 4 + 0];
    float4 h1 = g_h1[i * 4 + 1];
    float4 h2 = g_h1[i * 4 + 2];
    float4 h3 = g_h1[i * 4 + 3];
    float4 w0 = ((const float4*)Wl)[0];
    float4 w1 = ((const float4*)Wl)[1];
    float4 w2 = ((const float4*)Wl)[2];
    float4 w3 = ((const float4*)Wl)[3];
    float acc = bl[0];
    acc += h0.x * w0.x + h0.y * w0.y + h0.z * w0.z + h0.w * w0.w;
    acc += h1.x * w1.x + h1.y * w1.y + h1.z * w1.z + h1.w * w1.w;
    acc += h2.x * w2.x + h2.y * w2.y + h2.z * w2.z + h2.w * w2.w;
    acc += h3.x * w3.x + h3.y * w3.y + h3.z * w3.z + h3.w * w3.w;
    out[i] = acc;
}

extern "C" void kernel_launch(void* const* d_in, const int* in_sizes, int n_in,
                              void* d_out, int out_size) {
    const float* x  = (const float*)d_in[0];
    const int*   ei = (const int*)d_in[1];    // JAX x64 disabled -> int32!
    const float* W1 = (const float*)d_in[2];
    const float* b1 = (const float*)d_in[3];
    const float* W2 = (const float*)d_in[4];
    const float* b2 = (const float*)d_in[5];
    const float* Wl = (const float*)d_in[6];
    const float* bl = (const float*)d_in[7];
    float* out = (float*)d_out;

    const int* src = ei;        // edge_index[0]
    const int* dst = ei + NE;   // edge_index[1]

    k_zero        <<<(NN + 255) / 256, 256>>>();
    k_count       <<<(NE + 255) / 256, 256>>>(dst);
    k_dis         <<<(NN + 255) / 256, 256>>>();
    k_scan_partial<<<NSB, SCAN_B>>>();
    k_scan_bsum   <<<1, 1>>>();
    k_scan_final  <<<NSB, SCAN_B>>>();
    k_fill        <<<(NE + 255) / 256, 256>>>(src, dst);
    k_gemm1       <<<(NN + 255) / 256, 256>>>(x, W1);
    k_agg1        <<<(NN * 4 + 255) / 256, 256>>>(b1);
    k_gemm2       <<<(NN + 255) / 256, 256>>>(W2);
    k_agg2        <<<(NN * 4 + 255) / 256, 256>>>(b2);
    k_head        <<<(NN + 255) / 256, 256>>>(Wl, bl, out);
}